// round 8
// baseline (speedup 1.0000x reference)
#include <cuda_runtime.h>
#include <cuda_bf16.h>
#include <cstdint>

// Problem constants
#define NB    4
#define SEQ   2048
#define DIN   768
#define DOUT  768
#define NH    12
#define DHD   64
#define MROWS (NB * SEQ)   // 8192
#define NTOT  2304         // Wq|Wk|Wv concatenated N
#define KC    32
#define NCH   (DIN / KC)   // 24

// ---------------------------------------------------------------------------
// Scratch (global device arrays; no runtime allocation allowed)
// ---------------------------------------------------------------------------
__device__ __align__(16) __nv_bfloat16 g_Qhi[(size_t)NB * NH * SEQ * DHD];
__device__ __align__(16) __nv_bfloat16 g_Qlo[(size_t)NB * NH * SEQ * DHD];
__device__ __align__(16) __nv_bfloat16 g_Khi[(size_t)NB * NH * SEQ * DHD];
__device__ __align__(16) __nv_bfloat16 g_Klo[(size_t)NB * NH * SEQ * DHD];
__device__ __align__(16) __nv_bfloat16 g_Vhi[(size_t)NB * NH * SEQ * DHD];
__device__ __align__(16) __nv_bfloat16 g_Vlo[(size_t)NB * NH * SEQ * DHD];

__device__ __align__(16) __nv_bfloat16 g_Xhi[(size_t)MROWS * DIN];
__device__ __align__(16) __nv_bfloat16 g_Xlo[(size_t)MROWS * DIN];
__device__ __align__(16) __nv_bfloat16 g_Chi[(size_t)MROWS * DOUT];
__device__ __align__(16) __nv_bfloat16 g_Clo[(size_t)MROWS * DOUT];
// Transposed weights [N,K] K-major: rows 0..2303 = Wq^T|Wk^T|Wv^T, 2304..3071 = Wo^T
__device__ __align__(16) __nv_bfloat16 g_Wthi[(size_t)(NTOT + DOUT) * DIN];
__device__ __align__(16) __nv_bfloat16 g_Wtlo[(size_t)(NTOT + DOUT) * DIN];

// ---------------------------------------------------------------------------
// PTX helpers (sm_80+ portable: cp.async, ldmatrix, mma.sync)
// ---------------------------------------------------------------------------
__device__ __forceinline__ uint32_t smem_u32(const void* p) {
    uint32_t a;
    asm("{ .reg .u64 t; cvta.to.shared.u64 t, %1; cvt.u32.u64 %0, t; }"
        : "=r"(a) : "l"(p));
    return a;
}
__device__ __forceinline__ void cp16(uint32_t dst, const void* src) {
    asm volatile("cp.async.cg.shared.global [%0], [%1], 16;"
                 :: "r"(dst), "l"(src));
}
#define CP_COMMIT() asm volatile("cp.async.commit_group;" ::: "memory")
#define CP_WAIT(n)  asm volatile("cp.async.wait_group %0;" :: "n"(n) : "memory")

__device__ __forceinline__ void ldm_x4(uint32_t* r, uint32_t a) {
    asm volatile("ldmatrix.sync.aligned.m8n8.x4.shared.b16 {%0,%1,%2,%3}, [%4];"
                 : "=r"(r[0]), "=r"(r[1]), "=r"(r[2]), "=r"(r[3]) : "r"(a));
}
__device__ __forceinline__ void ldm_x4_t(uint32_t* r, uint32_t a) {
    asm volatile("ldmatrix.sync.aligned.m8n8.x4.trans.shared.b16 {%0,%1,%2,%3}, [%4];"
                 : "=r"(r[0]), "=r"(r[1]), "=r"(r[2]), "=r"(r[3]) : "r"(a));
}
__device__ __forceinline__ void mma16816(float* d, const uint32_t* a,
                                         const uint32_t* b) {
    asm volatile(
        "mma.sync.aligned.m16n8k16.row.col.f32.bf16.bf16.f32 "
        "{%0,%1,%2,%3}, {%4,%5,%6,%7}, {%8,%9}, {%0,%1,%2,%3};"
        : "+f"(d[0]), "+f"(d[1]), "+f"(d[2]), "+f"(d[3])
        : "r"(a[0]), "r"(a[1]), "r"(a[2]), "r"(a[3]), "r"(b[0]), "r"(b[1]));
}
__device__ __forceinline__ void pack_hl(float f0, float f1,
                                        uint32_t& ph, uint32_t& pl) {
    __nv_bfloat16 h0 = __float2bfloat16(f0), h1 = __float2bfloat16(f1);
    __nv_bfloat162 hp = __halves2bfloat162(h0, h1);
    ph = *(uint32_t*)&hp;
    __nv_bfloat16 g0 = __float2bfloat16(f0 - __bfloat162float(h0));
    __nv_bfloat16 g1 = __float2bfloat16(f1 - __bfloat162float(h1));
    __nv_bfloat162 lp = __halves2bfloat162(g0, g1);
    pl = *(uint32_t*)&lp;
}

// GEMM smem: 2 stages x 4 arrays (Ahi,Alo,Bhi,Blo), 128 rows x 80 B
#define ROW_B    80
#define ARR_B    (128 * ROW_B)
#define STAGE_B  (4 * ARR_B)
#define GEMM_SMEM (2 * STAGE_B)         // 81920 B

// ---------------------------------------------------------------------------
// hi/lo split of X
// ---------------------------------------------------------------------------
__global__ void cvt_split_kernel(const float* __restrict__ src, int n4) {
    int i = blockIdx.x * blockDim.x + threadIdx.x;
    if (i >= n4) return;
    float4 v = ((const float4*)src)[i];
    __nv_bfloat16 h0 = __float2bfloat16(v.x);
    __nv_bfloat16 h1 = __float2bfloat16(v.y);
    __nv_bfloat16 h2 = __float2bfloat16(v.z);
    __nv_bfloat16 h3 = __float2bfloat16(v.w);
    ushort4 hv, lv;
    hv.x = *(unsigned short*)&h0; hv.y = *(unsigned short*)&h1;
    hv.z = *(unsigned short*)&h2; hv.w = *(unsigned short*)&h3;
    __nv_bfloat16 l0 = __float2bfloat16(v.x - __bfloat162float(h0));
    __nv_bfloat16 l1 = __float2bfloat16(v.y - __bfloat162float(h1));
    __nv_bfloat16 l2 = __float2bfloat16(v.z - __bfloat162float(h2));
    __nv_bfloat16 l3 = __float2bfloat16(v.w - __bfloat162float(h3));
    lv.x = *(unsigned short*)&l0; lv.y = *(unsigned short*)&l1;
    lv.z = *(unsigned short*)&l2; lv.w = *(unsigned short*)&l3;
    ((ushort4*)g_Xhi)[i] = hv;
    ((ushort4*)g_Xlo)[i] = lv;
}

// ---------------------------------------------------------------------------
// Weight transpose + hi/lo split: W[K,N] -> Wt[N,K]
// ---------------------------------------------------------------------------
__global__ void cvt_w_kernel(const float* __restrict__ Wq, const float* __restrict__ Wk,
                             const float* __restrict__ Wv, const float* __restrict__ Wo) {
    __shared__ float t[32][33];
    const int z = blockIdx.z;
    const float* W = (z == 0) ? Wq : (z == 1) ? Wk : (z == 2) ? Wv : Wo;
    const int rowoff = (z < 3) ? z * DOUT : NTOT;
    const int k0 = blockIdx.y * 32, n0 = blockIdx.x * 32;
    const int tx = threadIdx.x, ty = threadIdx.y;
#pragma unroll
    for (int i = 0; i < 4; i++)
        t[ty + i * 8][tx] = W[(size_t)(k0 + ty + i * 8) * DOUT + n0 + tx];
    __syncthreads();
#pragma unroll
    for (int i = 0; i < 4; i++) {
        const int r = ty + i * 8;
        const float x = t[tx][r];
        const __nv_bfloat16 h = __float2bfloat16(x);
        const float res = x - __bfloat162float(h);
        const size_t di = (size_t)(rowoff + n0 + r) * DIN + k0 + tx;
        g_Wthi[di] = h;
        g_Wtlo[di] = __float2bfloat16(res);
    }
}

// ---------------------------------------------------------------------------
// bf16x3 HMMA GEMM, term-major mma ordering (dependency-stall free).
// EPI 0: hi/lo permuted store to g_{Q,K,V}{hi,lo}.  EPI 1: fp32 + bias -> Out.
// ---------------------------------------------------------------------------
template <int EPI>
__global__ __launch_bounds__(256, 1)
void mma_gemm_kernel(const float* __restrict__ bias, float* __restrict__ OutPlain) {
    extern __shared__ char smc[];
    const uint32_t smb = smem_u32(smc);
    const int tid = threadIdx.x, wid = tid >> 5, lane = tid & 31;
    const int warp_m = wid & 1, warp_n = wid >> 1;
    const int m0 = blockIdx.y * 128, n0 = blockIdx.x * 128;

    const __nv_bfloat16* Ahi = (EPI == 0) ? g_Xhi : g_Chi;
    const __nv_bfloat16* Alo = (EPI == 0) ? g_Xlo : g_Clo;
    const __nv_bfloat16* Bhi = (EPI == 0) ? g_Wthi : (g_Wthi + (size_t)NTOT * DIN);
    const __nv_bfloat16* Blo = (EPI == 0) ? g_Wtlo : (g_Wtlo + (size_t)NTOT * DIN);

    float acc[4][4][4];
#pragma unroll
    for (int mf = 0; mf < 4; mf++)
#pragma unroll
        for (int nf = 0; nf < 4; nf++)
#pragma unroll
            for (int j = 0; j < 4; j++) acc[mf][nf][j] = 0.f;

    auto load_chunk = [&](int ch, int st) {
#pragma unroll
        for (int t = 0; t < 4; t++) {
            const __nv_bfloat16* s = (t == 0) ? Ahi : (t == 1) ? Alo
                                   : (t == 2) ? Bhi : Blo;
            const int rb = (t < 2) ? m0 : n0;
            const uint32_t base = smb + (uint32_t)(st * STAGE_B + t * ARR_B);
#pragma unroll
            for (int j = 0; j < 2; j++) {
                const int id = tid + j * 256;
                const int row = id >> 2, c = id & 3;
                cp16(base + row * ROW_B + c * 16,
                     s + (size_t)(rb + row) * DIN + ch * KC + c * 8);
            }
        }
        CP_COMMIT();
    };

    load_chunk(0, 0);

    for (int ch = 0; ch < NCH; ch++) {
        const int st = ch & 1;
        if (ch + 1 < NCH) {
            load_chunk(ch + 1, st ^ 1);
            CP_WAIT(1);
        } else {
            CP_WAIT(0);
        }
        __syncthreads();

        const uint32_t sA = smb + st * STAGE_B;
        const uint32_t sB = sA + 2 * ARR_B;

#pragma unroll
        for (int k16 = 0; k16 < 2; k16++) {
            uint32_t ah[4][4], al[4][4], bh[4][2], bl[4][2];
#pragma unroll
            for (int f = 0; f < 4; f++) {
                const uint32_t addr = sA +
                    (warp_m * 64 + f * 16 + (lane & 15)) * ROW_B +
                    k16 * 32 + ((lane >> 4) << 4);
                ldm_x4(ah[f], addr);
                ldm_x4(al[f], addr + ARR_B);
            }
#pragma unroll
            for (int g = 0; g < 2; g++) {
                uint32_t rh[4], rl[4];
                const uint32_t addr = sB +
                    (warp_n * 32 + g * 16 + (lane & 7) + ((lane >> 4) << 3)) * ROW_B +
                    k16 * 32 + (((lane >> 3) & 1) << 4);
                ldm_x4(rh, addr);
                ldm_x4(rl, addr + ARR_B);
                bh[g * 2][0] = rh[0]; bh[g * 2][1] = rh[1];
                bh[g * 2 + 1][0] = rh[2]; bh[g * 2 + 1][1] = rh[3];
                bl[g * 2][0] = rl[0]; bl[g * 2][1] = rl[1];
                bl[g * 2 + 1][0] = rl[2]; bl[g * 2 + 1][1] = rl[3];
            }
            // Term-major: 16 independent mmas per pass; each accumulator's
            // reuses are 16 mmas apart -> HMMA latency hidden.
#pragma unroll
            for (int mf = 0; mf < 4; mf++)
#pragma unroll
                for (int nf = 0; nf < 4; nf++)
                    mma16816(acc[mf][nf], ah[mf], bh[nf]);
#pragma unroll
            for (int mf = 0; mf < 4; mf++)
#pragma unroll
                for (int nf = 0; nf < 4; nf++)
                    mma16816(acc[mf][nf], ah[mf], bl[nf]);
#pragma unroll
            for (int mf = 0; mf < 4; mf++)
#pragma unroll
                for (int nf = 0; nf < 4; nf++)
                    mma16816(acc[mf][nf], al[mf], bh[nf]);
        }
        __syncthreads();
    }

#pragma unroll
    for (int mf = 0; mf < 4; mf++)
#pragma unroll
        for (int nf = 0; nf < 4; nf++) {
            const int m  = m0 + warp_m * 64 + mf * 16 + (lane >> 2);
            const int nl = warp_n * 32 + nf * 8 + (lane & 3) * 2;
            if (EPI == 0) {
                const int mat = blockIdx.x / (DOUT / 128);
                const int n = (blockIdx.x % (DOUT / 128)) * 128 + nl;
                __nv_bfloat16 *Oh, *Ol;
                if (mat == 0)      { Oh = g_Qhi; Ol = g_Qlo; }
                else if (mat == 1) { Oh = g_Khi; Ol = g_Klo; }
                else               { Oh = g_Vhi; Ol = g_Vlo; }
                const int h = n >> 6, dh = n & 63;
                const int b = m >> 11, s = m & 2047;
                const size_t i0 = (((size_t)b * NH + h) * SEQ + s) * DHD + dh;
                const size_t i1 = i0 + 8 * DHD;
                uint32_t ph, pl;
                pack_hl(acc[mf][nf][0], acc[mf][nf][1], ph, pl);
                *(uint32_t*)&Oh[i0] = ph;
                *(uint32_t*)&Ol[i0] = pl;
                pack_hl(acc[mf][nf][2], acc[mf][nf][3], ph, pl);
                *(uint32_t*)&Oh[i1] = ph;
                *(uint32_t*)&Ol[i1] = pl;
            } else {
                const int n = n0 + nl;
                float2 v0 = make_float2(acc[mf][nf][0] + bias[n],
                                        acc[mf][nf][1] + bias[n + 1]);
                float2 v1 = make_float2(acc[mf][nf][2] + bias[n],
                                        acc[mf][nf][3] + bias[n + 1]);
                *(float2*)&OutPlain[(size_t)m * DOUT + n] = v0;
                *(float2*)&OutPlain[(size_t)(m + 8) * DOUT + n] = v1;
            }
        }
}

// ---------------------------------------------------------------------------
// Tensor-core causal flash attention (bf16x3), term-major mma ordering.
// CTA: 128 queries (8 warps x 16 rows), key tiles of 64, cp.async dbl buffer.
// smem: Qhi @0, Qlo @18432; stage s @36864+s*36864:
//   Khi +0, Klo +9216, Vhi +18432, Vlo +27648.  Row stride 144 B.
// ---------------------------------------------------------------------------
#define AR 144
#define ATTN_SMEM 110592

__global__ __launch_bounds__(256, 1)
void attn_mma_kernel() {
    extern __shared__ char smc[];
    const uint32_t smb = smem_u32(smc);
    const int tid = threadIdx.x, wid = tid >> 5, lane = tid & 31;
    const int qt = blockIdx.x, bh = blockIdx.y;
    const int b = bh / NH, h = bh - b * NH;
    const size_t qoff = ((size_t)bh * SEQ + qt * 128) * DHD;
    const size_t kvoff = (size_t)bh * SEQ * DHD;

    // Q tile (hi/lo) -> smem: 128 rows x 8 chunks
#pragma unroll
    for (int j = 0; j < 4; j++) {
        const int id = tid + j * 256;
        const int row = id >> 3, c = id & 7;
        cp16(smb + row * AR + c * 16, g_Qhi + qoff + row * 64 + c * 8);
        cp16(smb + 18432 + row * AR + c * 16, g_Qlo + qoff + row * 64 + c * 8);
    }
    CP_COMMIT();

    auto load_kv = [&](int kt, int st) {
        const uint32_t sb = smb + 36864 + (uint32_t)st * 36864;
#pragma unroll
        for (int j = 0; j < 2; j++) {
            const int id = tid + j * 256;     // 64 rows x 8 chunks
            const int row = id >> 3, c = id & 7;
            const size_t g = kvoff + (size_t)(kt * 64 + row) * 64 + c * 8;
            const uint32_t so = row * AR + c * 16;
            cp16(sb + so, g_Khi + g);
            cp16(sb + 9216 + so, g_Klo + g);
            cp16(sb + 18432 + so, g_Vhi + g);
            cp16(sb + 27648 + so, g_Vlo + g);
        }
        CP_COMMIT();
    };
    load_kv(0, 0);

    float o[8][4];
#pragma unroll
    for (int nf = 0; nf < 8; nf++)
#pragma unroll
        for (int e = 0; e < 4; e++) o[nf][e] = 0.f;
    float m0 = -3.0e38f, m1 = -3.0e38f, l0 = 0.f, l1 = 0.f;

    const int q_base = qt * 128 + wid * 16;
    const int nt = 2 * qt + 2;

    for (int kt = 0; kt < nt; kt++) {
        const int st = kt & 1;
        if (kt + 1 < nt) { load_kv(kt + 1, st ^ 1); CP_WAIT(1); }
        else             { CP_WAIT(0); }
        __syncthreads();

        const int k0 = kt * 64;
        if (k0 <= q_base) {           // warp-uniform causal skip
            const uint32_t sK = smb + 36864 + (uint32_t)st * 36864;
            const uint32_t sV = sK + 18432;

            float s[8][4];
#pragma unroll
            for (int nf = 0; nf < 8; nf++)
#pragma unroll
                for (int e = 0; e < 4; e++) s[nf][e] = 0.f;

#pragma unroll
            for (int kk = 0; kk < 4; kk++) {
                uint32_t qh[4], ql[4], kh[4][4], kl[4][4];
                const uint32_t qa = smb + (wid * 16 + (lane & 15)) * AR +
                                    kk * 32 + ((lane >> 4) << 4);
                ldm_x4(qh, qa);
                ldm_x4(ql, qa + 18432);
#pragma unroll
                for (int g = 0; g < 4; g++) {
                    const uint32_t ka = sK +
                        (g * 16 + (lane & 7) + ((lane >> 4) << 3)) * AR +
                        kk * 32 + (((lane >> 3) & 1) << 4);
                    ldm_x4(kh[g], ka);
                    ldm_x4(kl[g], ka + 9216);
                }
                // Term-major: 8 independent mmas per pass
#pragma unroll
                for (int g = 0; g < 4; g++) {
                    mma16816(s[2 * g], qh, &kh[g][0]);
                    mma16816(s[2 * g + 1], qh, &kh[g][2]);
                }
#pragma unroll
                for (int g = 0; g < 4; g++) {
                    mma16816(s[2 * g], qh, &kl[g][0]);
                    mma16816(s[2 * g + 1], qh, &kl[g][2]);
                }
#pragma unroll
                for (int g = 0; g < 4; g++) {
                    mma16816(s[2 * g], ql, &kh[g][0]);
                    mma16816(s[2 * g + 1], ql, &kh[g][2]);
                }
            }

            // scale + causal mask
            const bool diag = (k0 + 63 > q_base);
#pragma unroll
            for (int nf = 0; nf < 8; nf++)
#pragma unroll
                for (int e = 0; e < 4; e++) {
                    float v = s[nf][e] * 0.125f;
                    if (diag) {
                        const int key = k0 + nf * 8 + ((lane & 3) << 1) + (e & 1);
                        const int row = q_base + (lane >> 2) + ((e & 2) ? 8 : 0);
                        if (key > row) v = -3.0e38f;
                    }
                    s[nf][e] = v;
                }

            // online softmax (rows r and r+8 per lane)
            float mx0 = -3.0e38f, mx1 = -3.0e38f;
#pragma unroll
            for (int nf = 0; nf < 8; nf++) {
                mx0 = fmaxf(mx0, fmaxf(s[nf][0], s[nf][1]));
                mx1 = fmaxf(mx1, fmaxf(s[nf][2], s[nf][3]));
            }
            mx0 = fmaxf(mx0, __shfl_xor_sync(0xffffffffu, mx0, 1));
            mx0 = fmaxf(mx0, __shfl_xor_sync(0xffffffffu, mx0, 2));
            mx1 = fmaxf(mx1, __shfl_xor_sync(0xffffffffu, mx1, 1));
            mx1 = fmaxf(mx1, __shfl_xor_sync(0xffffffffu, mx1, 2));
            const float nm0 = fmaxf(m0, mx0), nm1 = fmaxf(m1, mx1);

            float sum0 = 0.f, sum1 = 0.f;
#pragma unroll
            for (int nf = 0; nf < 8; nf++) {
                s[nf][0] = __expf(s[nf][0] - nm0);
                s[nf][1] = __expf(s[nf][1] - nm0);
                s[nf][2] = __expf(s[nf][2] - nm1);
                s[nf][3] = __expf(s[nf][3] - nm1);
                sum0 += s[nf][0] + s[nf][1];
                sum1 += s[nf][2] + s[nf][3];
            }
            sum0 += __shfl_xor_sync(0xffffffffu, sum0, 1);
            sum0 += __shfl_xor_sync(0xffffffffu, sum0, 2);
            sum1 += __shfl_xor_sync(0xffffffffu, sum1, 1);
            sum1 += __shfl_xor_sync(0xffffffffu, sum1, 2);

            const float a0 = __expf(m0 - nm0), a1 = __expf(m1 - nm1);
            l0 = l0 * a0 + sum0;
            l1 = l1 * a1 + sum1;
            m0 = nm0; m1 = nm1;
#pragma unroll
            for (int nf = 0; nf < 8; nf++) {
                o[nf][0] *= a0; o[nf][1] *= a0;
                o[nf][2] *= a1; o[nf][3] *= a1;
            }

            // O += P @ V, term-major
#pragma unroll
            for (int kk = 0; kk < 4; kk++) {
                uint32_t ph[4], pl[4], vh[4][4], vl[4][4];
                pack_hl(s[2 * kk][0],     s[2 * kk][1],     ph[0], pl[0]);
                pack_hl(s[2 * kk][2],     s[2 * kk][3],     ph[1], pl[1]);
                pack_hl(s[2 * kk + 1][0], s[2 * kk + 1][1], ph[2], pl[2]);
                pack_hl(s[2 * kk + 1][2], s[2 * kk + 1][3], ph[3], pl[3]);
#pragma unroll
                for (int g = 0; g < 4; g++) {
                    const uint32_t va = sV +
                        (kk * 16 + (lane & 7) + ((lane >> 3) & 1) * 8) * AR +
                        g * 32 + (((lane >> 4) & 1) << 4);
                    ldm_x4_t(vh[g], va);
                    ldm_x4_t(vl[g], va + 9216);
                }
#pragma unroll
                for (int g = 0; g < 4; g++) {
                    mma16816(o[2 * g], ph, &vh[g][0]);
                    mma16816(o[2 * g + 1], ph, &vh[g][2]);
                }
#pragma unroll
                for (int g = 0; g < 4; g++) {
                    mma16816(o[2 * g], ph, &vl[g][0]);
                    mma16816(o[2 * g + 1], ph, &vl[g][2]);
                }
#pragma unroll
                for (int g = 0; g < 4; g++) {
                    mma16816(o[2 * g], pl, &vh[g][0]);
                    mma16816(o[2 * g + 1], pl, &vh[g][2]);
                }
            }
        }
        __syncthreads();
    }

    // Epilogue: ctx hi/lo bf16, layout [b*SEQ + s][h*64 + dh]
    const float inv0 = 1.f / l0, inv1 = 1.f / l1;
    const int s0 = q_base + (lane >> 2);
#pragma unroll
    for (int nf = 0; nf < 8; nf++) {
        const int dh = nf * 8 + ((lane & 3) << 1);
        const size_t i0 = ((size_t)b * SEQ + s0) * DOUT + h * 64 + dh;
        const size_t i1 = i0 + (size_t)8 * DOUT;
        uint32_t ph, pl;
        pack_hl(o[nf][0] * inv0, o[nf][1] * inv0, ph, pl);
        *(uint32_t*)&g_Chi[i0] = ph;
        *(uint32_t*)&g_Clo[i0] = pl;
        pack_hl(o[nf][2] * inv1, o[nf][3] * inv1, ph, pl);
        *(uint32_t*)&g_Chi[i1] = ph;
        *(uint32_t*)&g_Clo[i1] = pl;
    }
}

// ---------------------------------------------------------------------------
// Launch. Inputs: [0]=x f32, [1]=mask (unused), [2..5]=Wq,Wk,Wv,Wo, [6]=bo.
// ---------------------------------------------------------------------------
extern "C" void kernel_launch(void* const* d_in, const int* in_sizes, int n_in,
                              void* d_out, int out_size) {
    const float* x  = (const float*)d_in[0];
    const float* Wq = (const float*)d_in[2];
    const float* Wk = (const float*)d_in[3];
    const float* Wv = (const float*)d_in[4];
    const float* Wo = (const float*)d_in[5];
    const float* bo = (const float*)d_in[6];
    float* out = (float*)d_out;

    cudaFuncSetAttribute(mma_gemm_kernel<0>,
                         cudaFuncAttributeMaxDynamicSharedMemorySize, GEMM_SMEM);
    cudaFuncSetAttribute(mma_gemm_kernel<1>,
                         cudaFuncAttributeMaxDynamicSharedMemorySize, GEMM_SMEM);
    cudaFuncSetAttribute(attn_mma_kernel,
                         cudaFuncAttributeMaxDynamicSharedMemorySize, ATTN_SMEM);

    // 1) Split X into hi/lo bf16
    const int n4x = MROWS * DIN / 4;
    cvt_split_kernel<<<(n4x + 255) / 256, 256>>>(x, n4x);
    // 2) Transpose + split all weights
    cvt_w_kernel<<<dim3(DOUT / 32, DIN / 32, 4), dim3(32, 8)>>>(Wq, Wk, Wv, Wo);

    // 3) Fused QKV GEMM -> bf16 hi/lo Q,K,V (permuted)
    mma_gemm_kernel<0><<<dim3(NTOT / 128, MROWS / 128), 256, GEMM_SMEM>>>(
        nullptr, nullptr);

    // 4) Tensor-core flash attention -> ctx hi/lo
    attn_mma_kernel<<<dim3(SEQ / 128, NB * NH), 256, ATTN_SMEM>>>();

    // 5) Output projection + bias
    mma_gemm_kernel<1><<<dim3(DOUT / 128, MROWS / 128), 256, GEMM_SMEM>>>(bo, out);
}

// round 9
// speedup vs baseline: 1.0856x; 1.0856x over previous
#include <cuda_runtime.h>
#include <cuda_bf16.h>
#include <cstdint>

// Problem constants
#define NB    4
#define SEQ   2048
#define DIN   768
#define DOUT  768
#define NH    12
#define DHD   64
#define MROWS (NB * SEQ)   // 8192
#define NTOT  2304         // Wq|Wk|Wv concatenated N
#define KC    32
#define NCH   (DIN / KC)   // 24

// ---------------------------------------------------------------------------
// Scratch (global device arrays; no runtime allocation allowed)
// ---------------------------------------------------------------------------
__device__ __align__(16) __nv_bfloat16 g_Qhi[(size_t)NB * NH * SEQ * DHD];
__device__ __align__(16) __nv_bfloat16 g_Qlo[(size_t)NB * NH * SEQ * DHD];
__device__ __align__(16) __nv_bfloat16 g_Khi[(size_t)NB * NH * SEQ * DHD];
__device__ __align__(16) __nv_bfloat16 g_Klo[(size_t)NB * NH * SEQ * DHD];
__device__ __align__(16) __nv_bfloat16 g_Vhi[(size_t)NB * NH * SEQ * DHD];
__device__ __align__(16) __nv_bfloat16 g_Vlo[(size_t)NB * NH * SEQ * DHD];

__device__ __align__(16) __nv_bfloat16 g_Xhi[(size_t)MROWS * DIN];
__device__ __align__(16) __nv_bfloat16 g_Xlo[(size_t)MROWS * DIN];
__device__ __align__(16) __nv_bfloat16 g_Chi[(size_t)MROWS * DOUT];
__device__ __align__(16) __nv_bfloat16 g_Clo[(size_t)MROWS * DOUT];
// Transposed weights [N,K] K-major: rows 0..2303 = Wq^T|Wk^T|Wv^T, 2304..3071 = Wo^T
__device__ __align__(16) __nv_bfloat16 g_Wthi[(size_t)(NTOT + DOUT) * DIN];
__device__ __align__(16) __nv_bfloat16 g_Wtlo[(size_t)(NTOT + DOUT) * DIN];

// ---------------------------------------------------------------------------
// PTX helpers (sm_80+ portable: cp.async, ldmatrix, mma.sync)
// ---------------------------------------------------------------------------
__device__ __forceinline__ uint32_t smem_u32(const void* p) {
    uint32_t a;
    asm("{ .reg .u64 t; cvta.to.shared.u64 t, %1; cvt.u32.u64 %0, t; }"
        : "=r"(a) : "l"(p));
    return a;
}
__device__ __forceinline__ void cp16(uint32_t dst, const void* src) {
    asm volatile("cp.async.cg.shared.global [%0], [%1], 16;"
                 :: "r"(dst), "l"(src));
}
#define CP_COMMIT() asm volatile("cp.async.commit_group;" ::: "memory")
#define CP_WAIT(n)  asm volatile("cp.async.wait_group %0;" :: "n"(n) : "memory")

__device__ __forceinline__ void ldm_x4(uint32_t* r, uint32_t a) {
    asm volatile("ldmatrix.sync.aligned.m8n8.x4.shared.b16 {%0,%1,%2,%3}, [%4];"
                 : "=r"(r[0]), "=r"(r[1]), "=r"(r[2]), "=r"(r[3]) : "r"(a));
}
__device__ __forceinline__ void ldm_x4_t(uint32_t* r, uint32_t a) {
    asm volatile("ldmatrix.sync.aligned.m8n8.x4.trans.shared.b16 {%0,%1,%2,%3}, [%4];"
                 : "=r"(r[0]), "=r"(r[1]), "=r"(r[2]), "=r"(r[3]) : "r"(a));
}
__device__ __forceinline__ void mma16816(float* d, const uint32_t* a,
                                         const uint32_t* b) {
    asm volatile(
        "mma.sync.aligned.m16n8k16.row.col.f32.bf16.bf16.f32 "
        "{%0,%1,%2,%3}, {%4,%5,%6,%7}, {%8,%9}, {%0,%1,%2,%3};"
        : "+f"(d[0]), "+f"(d[1]), "+f"(d[2]), "+f"(d[3])
        : "r"(a[0]), "r"(a[1]), "r"(a[2]), "r"(a[3]), "r"(b[0]), "r"(b[1]));
}
__device__ __forceinline__ void pack_hl(float f0, float f1,
                                        uint32_t& ph, uint32_t& pl) {
    __nv_bfloat16 h0 = __float2bfloat16(f0), h1 = __float2bfloat16(f1);
    __nv_bfloat162 hp = __halves2bfloat162(h0, h1);
    ph = *(uint32_t*)&hp;
    __nv_bfloat16 g0 = __float2bfloat16(f0 - __bfloat162float(h0));
    __nv_bfloat16 g1 = __float2bfloat16(f1 - __bfloat162float(h1));
    __nv_bfloat162 lp = __halves2bfloat162(g0, g1);
    pl = *(uint32_t*)&lp;
}

// GEMM smem: 2 stages x 4 arrays (Ahi,Alo,Bhi,Blo), 128 rows x 80 B
#define ROW_B    80
#define ARR_B    (128 * ROW_B)
#define STAGE_B  (4 * ARR_B)
#define GEMM_SMEM (2 * STAGE_B)         // 81920 B -> 2 CTAs/SM = 160 KB

// ---------------------------------------------------------------------------
// hi/lo split of X
// ---------------------------------------------------------------------------
__global__ void cvt_split_kernel(const float* __restrict__ src, int n4) {
    int i = blockIdx.x * blockDim.x + threadIdx.x;
    if (i >= n4) return;
    float4 v = ((const float4*)src)[i];
    __nv_bfloat16 h0 = __float2bfloat16(v.x);
    __nv_bfloat16 h1 = __float2bfloat16(v.y);
    __nv_bfloat16 h2 = __float2bfloat16(v.z);
    __nv_bfloat16 h3 = __float2bfloat16(v.w);
    ushort4 hv, lv;
    hv.x = *(unsigned short*)&h0; hv.y = *(unsigned short*)&h1;
    hv.z = *(unsigned short*)&h2; hv.w = *(unsigned short*)&h3;
    __nv_bfloat16 l0 = __float2bfloat16(v.x - __bfloat162float(h0));
    __nv_bfloat16 l1 = __float2bfloat16(v.y - __bfloat162float(h1));
    __nv_bfloat16 l2 = __float2bfloat16(v.z - __bfloat162float(h2));
    __nv_bfloat16 l3 = __float2bfloat16(v.w - __bfloat162float(h3));
    lv.x = *(unsigned short*)&l0; lv.y = *(unsigned short*)&l1;
    lv.z = *(unsigned short*)&l2; lv.w = *(unsigned short*)&l3;
    ((ushort4*)g_Xhi)[i] = hv;
    ((ushort4*)g_Xlo)[i] = lv;
}

// ---------------------------------------------------------------------------
// Weight transpose + hi/lo split: W[K,N] -> Wt[N,K]
// ---------------------------------------------------------------------------
__global__ void cvt_w_kernel(const float* __restrict__ Wq, const float* __restrict__ Wk,
                             const float* __restrict__ Wv, const float* __restrict__ Wo) {
    __shared__ float t[32][33];
    const int z = blockIdx.z;
    const float* W = (z == 0) ? Wq : (z == 1) ? Wk : (z == 2) ? Wv : Wo;
    const int rowoff = (z < 3) ? z * DOUT : NTOT;
    const int k0 = blockIdx.y * 32, n0 = blockIdx.x * 32;
    const int tx = threadIdx.x, ty = threadIdx.y;
#pragma unroll
    for (int i = 0; i < 4; i++)
        t[ty + i * 8][tx] = W[(size_t)(k0 + ty + i * 8) * DOUT + n0 + tx];
    __syncthreads();
#pragma unroll
    for (int i = 0; i < 4; i++) {
        const int r = ty + i * 8;
        const float x = t[tx][r];
        const __nv_bfloat16 h = __float2bfloat16(x);
        const float res = x - __bfloat162float(h);
        const size_t di = (size_t)(rowoff + n0 + r) * DIN + k0 + tx;
        g_Wthi[di] = h;
        g_Wtlo[di] = __float2bfloat16(res);
    }
}

// ---------------------------------------------------------------------------
// bf16x3 HMMA GEMM; 2 CTAs/SM target (regs<=128: B frags hoisted, A streamed).
// EPI 0: hi/lo permuted store to g_{Q,K,V}{hi,lo}.  EPI 1: fp32 + bias -> Out.
// ---------------------------------------------------------------------------
template <int EPI>
__global__ __launch_bounds__(256, 2)
void mma_gemm_kernel(const float* __restrict__ bias, float* __restrict__ OutPlain) {
    extern __shared__ char smc[];
    const uint32_t smb = smem_u32(smc);
    const int tid = threadIdx.x, wid = tid >> 5, lane = tid & 31;
    const int warp_m = wid & 1, warp_n = wid >> 1;
    const int m0 = blockIdx.y * 128, n0 = blockIdx.x * 128;

    const __nv_bfloat16* Ahi = (EPI == 0) ? g_Xhi : g_Chi;
    const __nv_bfloat16* Alo = (EPI == 0) ? g_Xlo : g_Clo;
    const __nv_bfloat16* Bhi = (EPI == 0) ? g_Wthi : (g_Wthi + (size_t)NTOT * DIN);
    const __nv_bfloat16* Blo = (EPI == 0) ? g_Wtlo : (g_Wtlo + (size_t)NTOT * DIN);

    float acc[4][4][4];
#pragma unroll
    for (int mf = 0; mf < 4; mf++)
#pragma unroll
        for (int nf = 0; nf < 4; nf++)
#pragma unroll
            for (int j = 0; j < 4; j++) acc[mf][nf][j] = 0.f;

    auto load_chunk = [&](int ch, int st) {
#pragma unroll
        for (int t = 0; t < 4; t++) {
            const __nv_bfloat16* s = (t == 0) ? Ahi : (t == 1) ? Alo
                                   : (t == 2) ? Bhi : Blo;
            const int rb = (t < 2) ? m0 : n0;
            const uint32_t base = smb + (uint32_t)(st * STAGE_B + t * ARR_B);
#pragma unroll
            for (int j = 0; j < 2; j++) {
                const int id = tid + j * 256;
                const int row = id >> 2, c = id & 3;
                cp16(base + row * ROW_B + c * 16,
                     s + (size_t)(rb + row) * DIN + ch * KC + c * 8);
            }
        }
        CP_COMMIT();
    };

    load_chunk(0, 0);

    for (int ch = 0; ch < NCH; ch++) {
        const int st = ch & 1;
        if (ch + 1 < NCH) {
            load_chunk(ch + 1, st ^ 1);
            CP_WAIT(1);
        } else {
            CP_WAIT(0);
        }
        __syncthreads();

        const uint32_t sA = smb + st * STAGE_B;
        const uint32_t sB = sA + 2 * ARR_B;

#pragma unroll
        for (int k16 = 0; k16 < 2; k16++) {
            // Hoist B fragments (16 regs live)
            uint32_t bh[4][2], bl[4][2];
#pragma unroll
            for (int g = 0; g < 2; g++) {
                uint32_t rh[4], rl[4];
                const uint32_t addr = sB +
                    (warp_n * 32 + g * 16 + (lane & 7) + ((lane >> 4) << 3)) * ROW_B +
                    k16 * 32 + (((lane >> 3) & 1) << 4);
                ldm_x4(rh, addr);
                ldm_x4(rl, addr + ARR_B);
                bh[g * 2][0] = rh[0]; bh[g * 2][1] = rh[1];
                bh[g * 2 + 1][0] = rh[2]; bh[g * 2 + 1][1] = rh[3];
                bl[g * 2][0] = rl[0]; bl[g * 2][1] = rl[1];
                bl[g * 2 + 1][0] = rl[2]; bl[g * 2 + 1][1] = rl[3];
            }
            // Stream A fragments per mf (8 regs transient)
#pragma unroll
            for (int mf = 0; mf < 4; mf++) {
                uint32_t ah[4], al[4];
                const uint32_t addr = sA +
                    (warp_m * 64 + mf * 16 + (lane & 15)) * ROW_B +
                    k16 * 32 + ((lane >> 4) << 4);
                ldm_x4(ah, addr);
                ldm_x4(al, addr + ARR_B);
#pragma unroll
                for (int nf = 0; nf < 4; nf++) {
                    mma16816(acc[mf][nf], ah, bh[nf]);
                    mma16816(acc[mf][nf], ah, bl[nf]);
                    mma16816(acc[mf][nf], al, bh[nf]);
                }
            }
        }
        __syncthreads();
    }

#pragma unroll
    for (int mf = 0; mf < 4; mf++)
#pragma unroll
        for (int nf = 0; nf < 4; nf++) {
            const int m  = m0 + warp_m * 64 + mf * 16 + (lane >> 2);
            const int nl = warp_n * 32 + nf * 8 + (lane & 3) * 2;
            if (EPI == 0) {
                const int mat = blockIdx.x / (DOUT / 128);
                const int n = (blockIdx.x % (DOUT / 128)) * 128 + nl;
                __nv_bfloat16 *Oh, *Ol;
                if (mat == 0)      { Oh = g_Qhi; Ol = g_Qlo; }
                else if (mat == 1) { Oh = g_Khi; Ol = g_Klo; }
                else               { Oh = g_Vhi; Ol = g_Vlo; }
                const int h = n >> 6, dh = n & 63;
                const int b = m >> 11, s = m & 2047;
                const size_t i0 = (((size_t)b * NH + h) * SEQ + s) * DHD + dh;
                const size_t i1 = i0 + 8 * DHD;
                uint32_t ph, pl;
                pack_hl(acc[mf][nf][0], acc[mf][nf][1], ph, pl);
                *(uint32_t*)&Oh[i0] = ph;
                *(uint32_t*)&Ol[i0] = pl;
                pack_hl(acc[mf][nf][2], acc[mf][nf][3], ph, pl);
                *(uint32_t*)&Oh[i1] = ph;
                *(uint32_t*)&Ol[i1] = pl;
            } else {
                const int n = n0 + nl;
                float2 v0 = make_float2(acc[mf][nf][0] + bias[n],
                                        acc[mf][nf][1] + bias[n + 1]);
                float2 v1 = make_float2(acc[mf][nf][2] + bias[n],
                                        acc[mf][nf][3] + bias[n + 1]);
                *(float2*)&OutPlain[(size_t)m * DOUT + n] = v0;
                *(float2*)&OutPlain[(size_t)(m + 8) * DOUT + n] = v1;
            }
        }
}

// ---------------------------------------------------------------------------
// Tensor-core causal flash attention (bf16x3); 2 CTAs/SM target.
// CTA: 128 queries (8 warps x 16 rows), key tiles of 64, cp.async dbl buffer.
// smem: Qhi @0, Qlo @18432; stage s @36864+s*36864:
//   Khi +0, Klo +9216, Vhi +18432, Vlo +27648.  Row stride 144 B.
// 110592 B/CTA -> 2 CTAs = 221184 B (fits 228 KB SM budget).
// ---------------------------------------------------------------------------
#define AR 144
#define ATTN_SMEM 110592

__global__ __launch_bounds__(256, 2)
void attn_mma_kernel() {
    extern __shared__ char smc[];
    const uint32_t smb = smem_u32(smc);
    const int tid = threadIdx.x, wid = tid >> 5, lane = tid & 31;
    const int qt = blockIdx.x, bh = blockIdx.y;
    const int b = bh / NH, h = bh - b * NH;
    const size_t qoff = ((size_t)bh * SEQ + qt * 128) * DHD;
    const size_t kvoff = (size_t)bh * SEQ * DHD;

    // Q tile (hi/lo) -> smem: 128 rows x 8 chunks
#pragma unroll
    for (int j = 0; j < 4; j++) {
        const int id = tid + j * 256;
        const int row = id >> 3, c = id & 7;
        cp16(smb + row * AR + c * 16, g_Qhi + qoff + row * 64 + c * 8);
        cp16(smb + 18432 + row * AR + c * 16, g_Qlo + qoff + row * 64 + c * 8);
    }
    CP_COMMIT();

    auto load_kv = [&](int kt, int st) {
        const uint32_t sb = smb + 36864 + (uint32_t)st * 36864;
#pragma unroll
        for (int j = 0; j < 2; j++) {
            const int id = tid + j * 256;     // 64 rows x 8 chunks
            const int row = id >> 3, c = id & 7;
            const size_t g = kvoff + (size_t)(kt * 64 + row) * 64 + c * 8;
            const uint32_t so = row * AR + c * 16;
            cp16(sb + so, g_Khi + g);
            cp16(sb + 9216 + so, g_Klo + g);
            cp16(sb + 18432 + so, g_Vhi + g);
            cp16(sb + 27648 + so, g_Vlo + g);
        }
        CP_COMMIT();
    };
    load_kv(0, 0);

    float o[8][4];
#pragma unroll
    for (int nf = 0; nf < 8; nf++)
#pragma unroll
        for (int e = 0; e < 4; e++) o[nf][e] = 0.f;
    float m0 = -3.0e38f, m1 = -3.0e38f, l0 = 0.f, l1 = 0.f;

    const int q_base = qt * 128 + wid * 16;
    const int nt = 2 * qt + 2;

    for (int kt = 0; kt < nt; kt++) {
        const int st = kt & 1;
        if (kt + 1 < nt) { load_kv(kt + 1, st ^ 1); CP_WAIT(1); }
        else             { CP_WAIT(0); }
        __syncthreads();

        const int k0 = kt * 64;
        if (k0 <= q_base) {           // warp-uniform causal skip
            const uint32_t sK = smb + 36864 + (uint32_t)st * 36864;
            const uint32_t sV = sK + 18432;

            float s[8][4];
#pragma unroll
            for (int nf = 0; nf < 8; nf++)
#pragma unroll
                for (int e = 0; e < 4; e++) s[nf][e] = 0.f;

#pragma unroll
            for (int kk = 0; kk < 4; kk++) {
                uint32_t qh[4], ql[4];
                const uint32_t qa = smb + (wid * 16 + (lane & 15)) * AR +
                                    kk * 32 + ((lane >> 4) << 4);
                ldm_x4(qh, qa);
                ldm_x4(ql, qa + 18432);
#pragma unroll
                for (int g = 0; g < 4; g++) {
                    uint32_t kh[4], kl[4];
                    const uint32_t ka = sK +
                        (g * 16 + (lane & 7) + ((lane >> 4) << 3)) * AR +
                        kk * 32 + (((lane >> 3) & 1) << 4);
                    ldm_x4(kh, ka);
                    ldm_x4(kl, ka + 9216);
                    mma16816(s[2 * g], qh, &kh[0]);
                    mma16816(s[2 * g], qh, &kl[0]);
                    mma16816(s[2 * g], ql, &kh[0]);
                    mma16816(s[2 * g + 1], qh, &kh[2]);
                    mma16816(s[2 * g + 1], qh, &kl[2]);
                    mma16816(s[2 * g + 1], ql, &kh[2]);
                }
            }

            // scale + causal mask
            const bool diag = (k0 + 63 > q_base);
#pragma unroll
            for (int nf = 0; nf < 8; nf++)
#pragma unroll
                for (int e = 0; e < 4; e++) {
                    float v = s[nf][e] * 0.125f;
                    if (diag) {
                        const int key = k0 + nf * 8 + ((lane & 3) << 1) + (e & 1);
                        const int row = q_base + (lane >> 2) + ((e & 2) ? 8 : 0);
                        if (key > row) v = -3.0e38f;
                    }
                    s[nf][e] = v;
                }

            // online softmax (rows r and r+8 per lane)
            float mx0 = -3.0e38f, mx1 = -3.0e38f;
#pragma unroll
            for (int nf = 0; nf < 8; nf++) {
                mx0 = fmaxf(mx0, fmaxf(s[nf][0], s[nf][1]));
                mx1 = fmaxf(mx1, fmaxf(s[nf][2], s[nf][3]));
            }
            mx0 = fmaxf(mx0, __shfl_xor_sync(0xffffffffu, mx0, 1));
            mx0 = fmaxf(mx0, __shfl_xor_sync(0xffffffffu, mx0, 2));
            mx1 = fmaxf(mx1, __shfl_xor_sync(0xffffffffu, mx1, 1));
            mx1 = fmaxf(mx1, __shfl_xor_sync(0xffffffffu, mx1, 2));
            const float nm0 = fmaxf(m0, mx0), nm1 = fmaxf(m1, mx1);

            float sum0 = 0.f, sum1 = 0.f;
#pragma unroll
            for (int nf = 0; nf < 8; nf++) {
                s[nf][0] = __expf(s[nf][0] - nm0);
                s[nf][1] = __expf(s[nf][1] - nm0);
                s[nf][2] = __expf(s[nf][2] - nm1);
                s[nf][3] = __expf(s[nf][3] - nm1);
                sum0 += s[nf][0] + s[nf][1];
                sum1 += s[nf][2] + s[nf][3];
            }
            sum0 += __shfl_xor_sync(0xffffffffu, sum0, 1);
            sum0 += __shfl_xor_sync(0xffffffffu, sum0, 2);
            sum1 += __shfl_xor_sync(0xffffffffu, sum1, 1);
            sum1 += __shfl_xor_sync(0xffffffffu, sum1, 2);

            const float a0 = __expf(m0 - nm0), a1 = __expf(m1 - nm1);
            l0 = l0 * a0 + sum0;
            l1 = l1 * a1 + sum1;
            m0 = nm0; m1 = nm1;
#pragma unroll
            for (int nf = 0; nf < 8; nf++) {
                o[nf][0] *= a0; o[nf][1] *= a0;
                o[nf][2] *= a1; o[nf][3] *= a1;
            }

            // O += P @ V  (P from S-frags, converted hi/lo in registers)
#pragma unroll
            for (int kk = 0; kk < 4; kk++) {
                uint32_t ph[4], pl[4];
                pack_hl(s[2 * kk][0],     s[2 * kk][1],     ph[0], pl[0]);
                pack_hl(s[2 * kk][2],     s[2 * kk][3],     ph[1], pl[1]);
                pack_hl(s[2 * kk + 1][0], s[2 * kk + 1][1], ph[2], pl[2]);
                pack_hl(s[2 * kk + 1][2], s[2 * kk + 1][3], ph[3], pl[3]);
#pragma unroll
                for (int g = 0; g < 4; g++) {
                    uint32_t vh[4], vl[4];
                    const uint32_t va = sV +
                        (kk * 16 + (lane & 7) + ((lane >> 3) & 1) * 8) * AR +
                        g * 32 + (((lane >> 4) & 1) << 4);
                    ldm_x4_t(vh, va);
                    ldm_x4_t(vl, va + 9216);
                    mma16816(o[2 * g], ph, &vh[0]);
                    mma16816(o[2 * g], ph, &vl[0]);
                    mma16816(o[2 * g], pl, &vh[0]);
                    mma16816(o[2 * g + 1], ph, &vh[2]);
                    mma16816(o[2 * g + 1], ph, &vl[2]);
                    mma16816(o[2 * g + 1], pl, &vh[2]);
                }
            }
        }
        __syncthreads();
    }

    // Epilogue: ctx hi/lo bf16, layout [b*SEQ + s][h*64 + dh]
    const float inv0 = 1.f / l0, inv1 = 1.f / l1;
    const int s0 = q_base + (lane >> 2);
#pragma unroll
    for (int nf = 0; nf < 8; nf++) {
        const int dh = nf * 8 + ((lane & 3) << 1);
        const size_t i0 = ((size_t)b * SEQ + s0) * DOUT + h * 64 + dh;
        const size_t i1 = i0 + (size_t)8 * DOUT;
        uint32_t ph, pl;
        pack_hl(o[nf][0] * inv0, o[nf][1] * inv0, ph, pl);
        *(uint32_t*)&g_Chi[i0] = ph;
        *(uint32_t*)&g_Clo[i0] = pl;
        pack_hl(o[nf][2] * inv1, o[nf][3] * inv1, ph, pl);
        *(uint32_t*)&g_Chi[i1] = ph;
        *(uint32_t*)&g_Clo[i1] = pl;
    }
}

// ---------------------------------------------------------------------------
// Launch. Inputs: [0]=x f32, [1]=mask (unused), [2..5]=Wq,Wk,Wv,Wo, [6]=bo.
// ---------------------------------------------------------------------------
extern "C" void kernel_launch(void* const* d_in, const int* in_sizes, int n_in,
                              void* d_out, int out_size) {
    const float* x  = (const float*)d_in[0];
    const float* Wq = (const float*)d_in[2];
    const float* Wk = (const float*)d_in[3];
    const float* Wv = (const float*)d_in[4];
    const float* Wo = (const float*)d_in[5];
    const float* bo = (const float*)d_in[6];
    float* out = (float*)d_out;

    cudaFuncSetAttribute(mma_gemm_kernel<0>,
                         cudaFuncAttributeMaxDynamicSharedMemorySize, GEMM_SMEM);
    cudaFuncSetAttribute(mma_gemm_kernel<1>,
                         cudaFuncAttributeMaxDynamicSharedMemorySize, GEMM_SMEM);
    cudaFuncSetAttribute(attn_mma_kernel,
                         cudaFuncAttributeMaxDynamicSharedMemorySize, ATTN_SMEM);

    // 1) Split X into hi/lo bf16
    const int n4x = MROWS * DIN / 4;
    cvt_split_kernel<<<(n4x + 255) / 256, 256>>>(x, n4x);
    // 2) Transpose + split all weights
    cvt_w_kernel<<<dim3(DOUT / 32, DIN / 32, 4), dim3(32, 8)>>>(Wq, Wk, Wv, Wo);

    // 3) Fused QKV GEMM -> bf16 hi/lo Q,K,V (permuted)
    mma_gemm_kernel<0><<<dim3(NTOT / 128, MROWS / 128), 256, GEMM_SMEM>>>(
        nullptr, nullptr);

    // 4) Tensor-core flash attention -> ctx hi/lo
    attn_mma_kernel<<<dim3(SEQ / 128, NB * NH), 256, ATTN_SMEM>>>();

    // 5) Output projection + bias
    mma_gemm_kernel<1><<<dim3(DOUT / 128, MROWS / 128), 256, GEMM_SMEM>>>(bo, out);
}